// round 1
// baseline (speedup 1.0000x reference)
#include <cuda_runtime.h>
#include <cstdint>

// MaxUnpooling2D: updates [16,64,64,256] f32, mask [16,64,64,256] i32 (flat idx
// into [16,128,128,256]), out [16,128,128,256] f32.
//
// Structure exploited: each pooled cell (b,h,w,c) targets exactly one position
// inside its private 2x2 window (2h+dy, 2w+dx). Windows are disjoint -> no
// duplicates -> plain stores, and we can fuse the zero-fill: each thread owns
// 4 consecutive channels of one cell and writes all 4 window positions
// (float4 each), placing the update in its slot and 0.0 elsewhere.
// Total traffic: 128 MB read + 256 MB write, fully coalesced.

namespace {
constexpr int B  = 16;
constexpr int H  = 64;
constexpr int W  = 64;
constexpr int C  = 256;
constexpr int H2 = 2 * H;              // 128
constexpr int W2 = 2 * W;              // 128
constexpr int ROW   = W2 * C;          // 32768  (stride for dy=1)
constexpr int COLS  = C;               // 256    (stride for dx=1)
constexpr int IMG   = H2 * ROW;        // 4194304 (stride for b)
constexpr int NGROUPS = B * H * W * (C / 4);   // 4,194,304 float4 groups
}

__global__ void __launch_bounds__(256, 8)
max_unpool_kernel(const float4* __restrict__ upd,
                  const int4*  __restrict__ mask,
                  float*       __restrict__ out)
{
    int t = blockIdx.x * blockDim.x + threadIdx.x;
    if (t >= NGROUPS) return;

    // Decompose group index: t = ((b*H + h)*W + w)*(C/4) + c4
    int c4 = t & 63;            // C/4 = 64
    int w  = (t >> 6)  & 63;
    int h  = (t >> 12) & 63;
    int b  = t >> 18;
    int c  = c4 << 2;

    // Flat output index of window origin (2h, 2w) at channel c.
    // Max value 16*4194304 = 2^26 < 2^31 -> int is fine.
    int o00 = b * IMG + (h << 1) * ROW + (w << 1) * COLS + c;

    float4 v = upd[t];
    int4   m = mask[t];

    // Per-lane offset within window: in {0, COLS, ROW, ROW+COLS}
    int d0 = m.x - o00;
    int d1 = m.y - o00 - 1;
    int d2 = m.z - o00 - 2;
    int d3 = m.w - o00 - 3;

    float4 r00 = make_float4(d0 == 0          ? v.x : 0.f,
                             d1 == 0          ? v.y : 0.f,
                             d2 == 0          ? v.z : 0.f,
                             d3 == 0          ? v.w : 0.f);
    float4 r01 = make_float4(d0 == COLS       ? v.x : 0.f,
                             d1 == COLS       ? v.y : 0.f,
                             d2 == COLS       ? v.z : 0.f,
                             d3 == COLS       ? v.w : 0.f);
    float4 r10 = make_float4(d0 == ROW        ? v.x : 0.f,
                             d1 == ROW        ? v.y : 0.f,
                             d2 == ROW        ? v.z : 0.f,
                             d3 == ROW        ? v.w : 0.f);
    float4 r11 = make_float4(d0 == ROW + COLS ? v.x : 0.f,
                             d1 == ROW + COLS ? v.y : 0.f,
                             d2 == ROW + COLS ? v.z : 0.f,
                             d3 == ROW + COLS ? v.w : 0.f);

    *reinterpret_cast<float4*>(out + o00)              = r00;
    *reinterpret_cast<float4*>(out + o00 + COLS)       = r01;
    *reinterpret_cast<float4*>(out + o00 + ROW)        = r10;
    *reinterpret_cast<float4*>(out + o00 + ROW + COLS) = r11;
}

extern "C" void kernel_launch(void* const* d_in, const int* in_sizes, int n_in,
                              void* d_out, int out_size)
{
    const float4* upd  = reinterpret_cast<const float4*>(d_in[0]);
    const int4*   mask = reinterpret_cast<const int4*>(d_in[1]);
    float*        out  = reinterpret_cast<float*>(d_out);

    constexpr int THREADS = 256;
    constexpr int BLOCKS  = (NGROUPS + THREADS - 1) / THREADS;  // 16384
    max_unpool_kernel<<<BLOCKS, THREADS>>>(upd, mask, out);
}